// round 12
// baseline (speedup 1.0000x reference)
#include <cuda_runtime.h>
#include <cuda_fp16.h>
#include <cstdint>

// Sinkhorn, linear domain, fp16 kernel matrix, stage-buffered column sums.
//   K = valid ? fp16(exp(m)) : 0      (built fused with Sinkhorn step 1, v0=1)
//   step t: u_i = 1 / sum_j K_ij * inv(sb[t-1]_j) ; sb[t]_j += sum_i K_ij u_i
//   out = valid ? u_i * exp(m_ij) * inv(sb[9]_j) : 0   (fp32 exp recompute)
// B=64, N=1024, M=1024, tau=1, 10 steps.
//
// fused_pass now uses HMMA (mma.sync.m16n8k16, fp16 in / fp32 acc) for both
// the row-sum and column-sum reductions. u and v are converted to fp16 with
// per-block power-of-2 dynamic scaling (exact scale/descale; within-block
// magnitude spread is small enough that scaled values stay fp16-normal).

#define BB 64
#define NN 1024
#define MM 1024
#define NSTAGE 10

__device__ __half g_K[(size_t)BB * NN * MM];     // 128 MB scratch
__device__ float  g_u[BB * NN];
__device__ float  g_sb[NSTAGE][BB * MM];         // per-stage col-sum buffers

__device__ __forceinline__ float exp2i(int e) {  // exact 2^e
    return __int_as_float((e + 127) << 23);
}

// ---------------------------------------------------------------------------
// Zero all stage buffers (once per replay). 2.56 MB. grid=160, block=256.
// ---------------------------------------------------------------------------
__global__ void init_kernel() {
    float4* p = reinterpret_cast<float4*>(&g_sb[0][0]);
    int idx = blockIdx.x * blockDim.x + threadIdx.x;
    const int total = NSTAGE * BB * MM / 4;
    #pragma unroll
    for (int r = 0; r < 4; r++) {
        int q = idx + r * 40960;
        if (q < total) p[q] = make_float4(0.f, 0.f, 0.f, 0.f);
    }
}

// ---------------------------------------------------------------------------
// Build + Sinkhorn step 1 (v0 = 1): block = 32 rows x 8 warps x 4 rows.
// exp(m) masked -> fp16 K (zero-padded to 128-col tile boundary), row sums
// -> u1, col partials -> g_sb[0]. grid = (32, 64), block = 256.
// ---------------------------------------------------------------------------
__global__ void __launch_bounds__(256) build_fused_kernel(const float* __restrict__ m,
                                                          const int* __restrict__ nrows,
                                                          const int* __restrict__ ncols) {
    int b  = blockIdx.y;
    int nr = nrows[b];
    int nc = ncols[b];
    int i0 = blockIdx.x * 32;
    if (i0 >= nr || nc == 0) return;
    int npass = (nc + 127) >> 7;

    int lane = threadIdx.x & 31;
    int w    = threadIdx.x >> 5;

    float acc[32];
    #pragma unroll
    for (int k = 0; k < 32; k++) acc[k] = 0.f;

    const float* mb = m + ((size_t)b << 20);
    __half*      Kb = g_K + ((size_t)b << 20);

    #pragma unroll
    for (int q = 0; q < 4; q++) {
        int i = i0 + w * 4 + q;
        if (i < nr) {
            const float* mrow = mb + ((size_t)i << 10);
            __half*      krow = Kb + ((size_t)i << 10);
            uint2 kk[8];
            float s0 = 0.f, s1 = 0.f, s2 = 0.f, s3 = 0.f;
            #pragma unroll
            for (int p = 0; p < 8; p++) {
                if (p < npass) {
                    int j = p * 128 + lane * 4;
                    float4 mv = *reinterpret_cast<const float4*>(mrow + j);
                    float e0 = (j + 0 < nc) ? __expf(mv.x) : 0.f;
                    float e1 = (j + 1 < nc) ? __expf(mv.y) : 0.f;
                    float e2 = (j + 2 < nc) ? __expf(mv.z) : 0.f;
                    float e3 = (j + 3 < nc) ? __expf(mv.w) : 0.f;
                    __half2 h0 = __floats2half2_rn(e0, e1);
                    __half2 h1 = __floats2half2_rn(e2, e3);
                    kk[p].x = *reinterpret_cast<uint32_t*>(&h0);
                    kk[p].y = *reinterpret_cast<uint32_t*>(&h1);
                    *reinterpret_cast<uint2*>(krow + j) = kk[p];
                } else {
                    kk[p] = make_uint2(0u, 0u);
                }
                float2 f0 = __half22float2(*reinterpret_cast<__half2*>(&kk[p].x));
                float2 f1 = __half22float2(*reinterpret_cast<__half2*>(&kk[p].y));
                s0 += f0.x; s1 += f0.y; s2 += f1.x; s3 += f1.y;   // v0 = 1
            }
            float sum = (s0 + s1) + (s2 + s3);
            #pragma unroll
            for (int o = 16; o; o >>= 1) sum += __shfl_xor_sync(0xffffffffu, sum, o);
            float u = (sum > 0.f) ? __fdividef(1.0f, sum) : 0.f;
            if (lane == 0) g_u[(b << 10) + i] = u;
            #pragma unroll
            for (int p = 0; p < 8; p++) {
                float2 f0 = __half22float2(*reinterpret_cast<__half2*>(&kk[p].x));
                float2 f1 = __half22float2(*reinterpret_cast<__half2*>(&kk[p].y));
                acc[p * 4 + 0] = fmaf(f0.x, u, acc[p * 4 + 0]);
                acc[p * 4 + 1] = fmaf(f0.y, u, acc[p * 4 + 1]);
                acc[p * 4 + 2] = fmaf(f1.x, u, acc[p * 4 + 2]);
                acc[p * 4 + 3] = fmaf(f1.y, u, acc[p * 4 + 3]);
            }
        }
    }
    __shared__ float sm[8 * 1024];
    #pragma unroll
    for (int p = 0; p < 8; p++) {
        *reinterpret_cast<float4*>(&sm[w * 1024 + p * 128 + lane * 4]) =
            make_float4(acc[p * 4 + 0], acc[p * 4 + 1], acc[p * 4 + 2], acc[p * 4 + 3]);
    }
    __syncthreads();
    int t = threadIdx.x;
    int jmax = npass << 7;
    #pragma unroll
    for (int r = 0; r < 4; r++) {
        int j = r * 256 + t;
        if (j < jmax) {
            float s = 0.f;
            #pragma unroll
            for (int ww = 0; ww < 8; ww++) s += sm[ww * 1024 + j];
            atomicAdd(&g_sb[0][(b << 10) + j], s);
        }
    }
}

// ---------------------------------------------------------------------------
// Fused Sinkhorn step `stage` (1..9), HMMA version.
// Block = 16 rows of one batch, 8 warps. grid = (64, 64) (x=strip, y=batch).
//   1. cp.async strip (16 x ncpad fp16) to smem; zero rows >= nrv.
//   2. v = 1/s from sb[stage-1]; block vmax -> f; vh = fp16(v * 2^f).
//   3. Row pass: warp w does 16-col k-tiles w, w+8, ...; D += A(K) x B(vh
//      replicated). Col 0 of D = scaled row sums; cross-warp reduce in smem.
//   4. u = 2^f / D (fp32 -> g_u); block umax -> e; uh = fp16(u * 2^e).
//   5. Col pass: warp w does 16-col tiles; D = A(uh broadcast) x
//      B(ldmatrix.x4.trans of K). Row 0 of D = scaled col sums -> sacc.
//   6. atomicAdd(sacc * 2^-e) into sb[stage].
// ---------------------------------------------------------------------------
__global__ void __launch_bounds__(256) fused_pass_kernel(const int* __restrict__ nrows,
                                                         const int* __restrict__ ncols,
                                                         int stage) {
    int b  = blockIdx.y;
    int nr = nrows[b];
    int nc = ncols[b];
    int i0 = blockIdx.x << 4;
    if (i0 >= nr || nc == 0) return;
    int npass = (nc + 127) >> 7;
    int ntile = npass << 3;        // number of 16-col tiles
    int jmax  = npass << 7;
    int nrv   = min(16, nr - i0);

    int t = threadIdx.x, lane = t & 31, w = t >> 5;

    __shared__ __align__(16) __half strip[16 * 1024];   // 32 KB
    __shared__ __align__(8)  __half vh[1024];           // v * 2^f as fp16
    __shared__ __align__(8)  __half uh[16];             // u * 2^e as fp16
    __shared__ float sacc[1024];                        // scaled col sums
    __shared__ float spart[128];                        // 8 warps x 16 rowsums
    __shared__ float sred[9];                           // warp vmax + e bcast

    // ---- 1. strip load / zero-fill ----
    {
        int r  = t >> 4;
        int cb = (t & 15) << 4;                         // byte offset, stride 256
        if (r < nrv) {
            const char* src = (const char*)(g_K + ((size_t)b << 20) + ((size_t)(i0 + r) << 10));
            uint32_t dst = (uint32_t)__cvta_generic_to_shared(&strip[r << 10]);
            for (int p = 0; p < npass; p++)
                asm volatile("cp.async.cg.shared.global [%0], [%1], 16;\n"
                             :: "r"(dst + cb + (p << 8)), "l"(src + cb + (p << 8)));
        } else {
            for (int p = 0; p < npass; p++)
                *reinterpret_cast<uint4*>(reinterpret_cast<char*>(&strip[r << 10]) + cb + (p << 8)) =
                    make_uint4(0u, 0u, 0u, 0u);
        }
        asm volatile("cp.async.commit_group;\n");
    }

    // ---- 2. v prep with dynamic power-of-2 scaling ----
    float fscale;
    {
        float4 s4 = *reinterpret_cast<const float4*>(&g_sb[stage - 1][(b << 10) + (t << 2)]);
        float v0 = (s4.x > 0.f) ? __fdividef(1.f, s4.x) : 0.f;
        float v1 = (s4.y > 0.f) ? __fdividef(1.f, s4.y) : 0.f;
        float v2 = (s4.z > 0.f) ? __fdividef(1.f, s4.z) : 0.f;
        float v3 = (s4.w > 0.f) ? __fdividef(1.f, s4.w) : 0.f;
        *reinterpret_cast<float4*>(&sacc[t << 2]) = make_float4(0.f, 0.f, 0.f, 0.f);
        float vm = fmaxf(fmaxf(v0, v1), fmaxf(v2, v3));
        #pragma unroll
        for (int o = 16; o; o >>= 1) vm = fmaxf(vm, __shfl_xor_sync(0xffffffffu, vm, o));
        if (lane == 0) sred[w] = vm;
        __syncthreads();
        float vmax = sred[0];
        #pragma unroll
        for (int k = 1; k < 8; k++) vmax = fmaxf(vmax, sred[k]);
        int f = (vmax > 0.f) ? (14 - ilogbf(vmax)) : 0;
        fscale = exp2i(f);
        __half2 h01 = __floats2half2_rn(v0 * fscale, v1 * fscale);
        __half2 h23 = __floats2half2_rn(v2 * fscale, v3 * fscale);
        uint2 packed = make_uint2(*reinterpret_cast<uint32_t*>(&h01),
                                  *reinterpret_cast<uint32_t*>(&h23));
        *reinterpret_cast<uint2*>(&vh[t << 2]) = packed;
    }
    asm volatile("cp.async.wait_group 0;\n");
    __syncthreads();

    // shared ldmatrix base (same pattern for A and trans-B):
    // lane L -> row (L & 15), col offset ((L >> 4) << 3) halves
    uint32_t lm_base = (uint32_t)__cvta_generic_to_shared(strip)
                     + ((lane & 15) << 11) + ((lane >> 4) << 4);

    // ---- 3. row pass: D += K_tile x vh_replicated ----
    {
        float c0 = 0.f, c1 = 0.f, c2 = 0.f, c3 = 0.f;
        for (int kt = w; kt < ntile; kt += 8) {
            int j0 = kt << 4;
            uint32_t a0, a1, a2, a3;
            asm volatile("ldmatrix.sync.aligned.m8n8.x4.shared.b16 {%0,%1,%2,%3},[%4];\n"
                         : "=r"(a0), "=r"(a1), "=r"(a2), "=r"(a3)
                         : "r"(lm_base + (j0 << 1)));
            uint32_t b0 = *reinterpret_cast<const uint32_t*>(&vh[j0 + ((lane & 3) << 1)]);
            uint32_t b1 = *reinterpret_cast<const uint32_t*>(&vh[j0 + ((lane & 3) << 1) + 8]);
            asm volatile("mma.sync.aligned.m16n8k16.row.col.f32.f16.f16.f32 "
                         "{%0,%1,%2,%3},{%4,%5,%6,%7},{%8,%9},{%0,%1,%2,%3};\n"
                         : "+f"(c0), "+f"(c1), "+f"(c2), "+f"(c3)
                         : "r"(a0), "r"(a1), "r"(a2), "r"(a3), "r"(b0), "r"(b1));
        }
        if ((lane & 3) == 0) {                // col 0 holders: rowsum*2^f
            spart[(w << 4) + (lane >> 2)]     = c0;   // rows 0-7
            spart[(w << 4) + (lane >> 2) + 8] = c2;   // rows 8-15
        }
    }
    __syncthreads();

    // ---- 4. u from rowsums; per-block scale e; uh ----
    if (t < 16) {
        float D = 0.f;
        #pragma unroll
        for (int ww = 0; ww < 8; ww++) D += spart[(ww << 4) + t];
        float u = (t < nrv && D > 0.f) ? (fscale * __fdividef(1.f, D)) : 0.f;
        if (t < nrv) g_u[(b << 10) + i0 + t] = u;
        float um = u;
        #pragma unroll
        for (int o = 8; o; o >>= 1) um = fmaxf(um, __shfl_xor_sync(0xffffu, um, o));
        int e = (um > 0.f) ? (14 - ilogbf(um)) : 0;
        uh[t] = __float2half_rn(u * exp2i(e));
        if (t == 0) sred[8] = (float)e;
    }
    __syncthreads();
    float descale = exp2i(-(int)sred[8]);

    // ---- 5. col pass: D = uh_broadcast x K_tile^T (ldmatrix.trans) ----
    {
        uint32_t ua0 = *reinterpret_cast<const uint32_t*>(&uh[(lane & 3) << 1]);
        uint32_t ua1 = *reinterpret_cast<const uint32_t*>(&uh[((lane & 3) << 1) + 8]);
        for (int ct = w; ct < ntile; ct += 8) {
            int j0 = ct << 4;
            uint32_t b0, b1, b2, b3;
            asm volatile("ldmatrix.sync.aligned.m8n8.x4.trans.shared.b16 {%0,%1,%2,%3},[%4];\n"
                         : "=r"(b0), "=r"(b1), "=r"(b2), "=r"(b3)
                         : "r"(lm_base + (j0 << 1)));
            float d0 = 0.f, d1 = 0.f, d2 = 0.f, d3 = 0.f;
            asm volatile("mma.sync.aligned.m16n8k16.row.col.f32.f16.f16.f32 "
                         "{%0,%1,%2,%3},{%4,%5,%6,%7},{%8,%9},{%0,%1,%2,%3};\n"
                         : "+f"(d0), "+f"(d1), "+f"(d2), "+f"(d3)
                         : "r"(ua0), "r"(ua0), "r"(ua1), "r"(ua1), "r"(b0), "r"(b1));
            float e0 = 0.f, e1 = 0.f, e2 = 0.f, e3 = 0.f;
            asm volatile("mma.sync.aligned.m16n8k16.row.col.f32.f16.f16.f32 "
                         "{%0,%1,%2,%3},{%4,%5,%6,%7},{%8,%9},{%0,%1,%2,%3};\n"
                         : "+f"(e0), "+f"(e1), "+f"(e2), "+f"(e3)
                         : "r"(ua0), "r"(ua0), "r"(ua1), "r"(ua1), "r"(b2), "r"(b3));
            if (lane < 4) {                  // row 0 of D: cols j0+2l, j0+2l+1
                int j = j0 + (lane << 1);
                sacc[j]     += d0;  sacc[j + 1] += d1;
                sacc[j + 8] += e0;  sacc[j + 9] += e1;
            }
        }
    }
    __syncthreads();

    // ---- 6. epilogue: descale + global atomic ----
    {
        int j = t << 2;
        if (j < jmax) {
            float4 sa = *reinterpret_cast<float4*>(&sacc[j]);
            float* out = &g_sb[stage][(b << 10) + j];
            atomicAdd(&out[0], sa.x * descale);
            atomicAdd(&out[1], sa.y * descale);
            atomicAdd(&out[2], sa.z * descale);
            atomicAdd(&out[3], sa.w * descale);
        }
    }
}

// ---------------------------------------------------------------------------
// Final: out = valid ? u_i * exp(m_ij) * inv(sb[9]_j) : 0 — fp32 exp.
// grid = 4096, block = 256, 16 float4/thread (full 256 MB write).
// ---------------------------------------------------------------------------
__global__ void final_kernel(const float* __restrict__ m,
                             const int* __restrict__ nrows,
                             const int* __restrict__ ncols,
                             float* __restrict__ out) {
    int b   = blockIdx.x >> 6;
    int sub = blockIdx.x & 63;
    int nr = nrows[b];
    int nc = ncols[b];
    const float* mb = m + ((size_t)b << 20);
    float*       ob = out + ((size_t)b << 20);
    const float* sb = &g_sb[NSTAGE - 1][b << 10];

    #pragma unroll
    for (int k = 0; k < 16; k++) {
        int q = sub * 4096 + k * 256 + threadIdx.x;
        int i = q >> 8;
        int j = (q & 255) << 2;
        float4 o;
        if (i >= nr || j >= nc) {
            o = make_float4(0.f, 0.f, 0.f, 0.f);
        } else {
            float4 mm = *reinterpret_cast<const float4*>(mb + ((size_t)q << 2));
            float  u  = g_u[(b << 10) + i];
            float4 s4 = *reinterpret_cast<const float4*>(sb + j);
            float vx = (s4.x > 0.f) ? __fdividef(1.0f, s4.x) : 0.f;
            float vy = (s4.y > 0.f) ? __fdividef(1.0f, s4.y) : 0.f;
            float vz = (s4.z > 0.f) ? __fdividef(1.0f, s4.z) : 0.f;
            float vw = (s4.w > 0.f) ? __fdividef(1.0f, s4.w) : 0.f;
            o.x = __expf(mm.x) * u * vx;
            o.y = __expf(mm.y) * u * vy;
            o.z = __expf(mm.z) * u * vz;
            o.w = __expf(mm.w) * u * vw;
        }
        *reinterpret_cast<float4*>(ob + ((size_t)q << 2)) = o;
    }
}

extern "C" void kernel_launch(void* const* d_in, const int* in_sizes, int n_in,
                              void* d_out, int out_size) {
    const float* m     = (const float*)d_in[0];
    const int*   nrows = (const int*)d_in[1];
    const int*   ncols = (const int*)d_in[2];
    float* out = (float*)d_out;

    init_kernel<<<160, 256>>>();                                   // zero stage bufs
    build_fused_kernel<<<dim3(32, 64), 256>>>(m, nrows, ncols);    // step 1
    for (int t = 1; t <= 9; t++)                                   // steps 2..10
        fused_pass_kernel<<<dim3(64, 64), 256>>>(nrows, ncols, t);
    final_kernel<<<4096, 256>>>(m, nrows, ncols, out);
}

// round 13
// speedup vs baseline: 1.5047x; 1.5047x over previous
#include <cuda_runtime.h>
#include <cuda_fp16.h>
#include <cstdint>

// Sinkhorn, linear domain, fp16 kernel matrix, stage-buffered column sums.
//   K = valid ? fp16(exp(m)) : 0      (built fused with Sinkhorn step 1, v0=1)
//   step t: u_i = 1 / sum_j K_ij * inv(sb[t-1]_j) ; sb[t]_j += sum_i K_ij u_i
//   out = valid ? u_i * exp(m_ij) * inv(sb[9]_j) : 0   (fp32 exp recompute)
// B=64, N=1024, M=1024, tau=1, 10 steps.
//
// fused_pass uses HMMA (mma.sync.m16n8k16) for both reductions. Strip rows
// are stored at a 2064-byte stride (2064 mod 128 = 16) so ldmatrix.x4 /
// .x4.trans are bank-conflict-free (the R12 version used 2048 -> 8-way
// conflicts -> L1 61%). u and v are fp16 with per-block power-of-2 scaling.

#define BB 64
#define NN 1024
#define MM 1024
#define NSTAGE 10
#define RSTRIDE 1032    // strip row stride in halves (2064 B; 2064 % 128 = 16)

__device__ __half g_K[(size_t)BB * NN * MM];     // 128 MB scratch
__device__ float  g_u[BB * NN];
__device__ float  g_sb[NSTAGE][BB * MM];         // per-stage col-sum buffers

__device__ __forceinline__ float exp2i(int e) {  // exact 2^e
    return __int_as_float((e + 127) << 23);
}

// ---------------------------------------------------------------------------
// Zero all stage buffers (once per replay). 2.56 MB. grid=160, block=256.
// ---------------------------------------------------------------------------
__global__ void init_kernel() {
    float4* p = reinterpret_cast<float4*>(&g_sb[0][0]);
    int idx = blockIdx.x * blockDim.x + threadIdx.x;
    const int total = NSTAGE * BB * MM / 4;
    #pragma unroll
    for (int r = 0; r < 4; r++) {
        int q = idx + r * 40960;
        if (q < total) p[q] = make_float4(0.f, 0.f, 0.f, 0.f);
    }
}

// ---------------------------------------------------------------------------
// Build + Sinkhorn step 1 (v0 = 1): block = 32 rows x 8 warps x 4 rows.
// exp(m) masked -> fp16 K (zero-padded to 128-col tile boundary), row sums
// -> u1, col partials -> g_sb[0]. grid = (32, 64), block = 256.
// ---------------------------------------------------------------------------
__global__ void __launch_bounds__(256) build_fused_kernel(const float* __restrict__ m,
                                                          const int* __restrict__ nrows,
                                                          const int* __restrict__ ncols) {
    int b  = blockIdx.y;
    int nr = nrows[b];
    int nc = ncols[b];
    int i0 = blockIdx.x * 32;
    if (i0 >= nr || nc == 0) return;
    int npass = (nc + 127) >> 7;

    int lane = threadIdx.x & 31;
    int w    = threadIdx.x >> 5;

    float acc[32];
    #pragma unroll
    for (int k = 0; k < 32; k++) acc[k] = 0.f;

    const float* mb = m + ((size_t)b << 20);
    __half*      Kb = g_K + ((size_t)b << 20);

    #pragma unroll
    for (int q = 0; q < 4; q++) {
        int i = i0 + w * 4 + q;
        if (i < nr) {
            const float* mrow = mb + ((size_t)i << 10);
            __half*      krow = Kb + ((size_t)i << 10);
            uint2 kk[8];
            float s0 = 0.f, s1 = 0.f, s2 = 0.f, s3 = 0.f;
            #pragma unroll
            for (int p = 0; p < 8; p++) {
                if (p < npass) {
                    int j = p * 128 + lane * 4;
                    float4 mv = *reinterpret_cast<const float4*>(mrow + j);
                    float e0 = (j + 0 < nc) ? __expf(mv.x) : 0.f;
                    float e1 = (j + 1 < nc) ? __expf(mv.y) : 0.f;
                    float e2 = (j + 2 < nc) ? __expf(mv.z) : 0.f;
                    float e3 = (j + 3 < nc) ? __expf(mv.w) : 0.f;
                    __half2 h0 = __floats2half2_rn(e0, e1);
                    __half2 h1 = __floats2half2_rn(e2, e3);
                    kk[p].x = *reinterpret_cast<uint32_t*>(&h0);
                    kk[p].y = *reinterpret_cast<uint32_t*>(&h1);
                    *reinterpret_cast<uint2*>(krow + j) = kk[p];
                } else {
                    kk[p] = make_uint2(0u, 0u);
                }
                float2 f0 = __half22float2(*reinterpret_cast<__half2*>(&kk[p].x));
                float2 f1 = __half22float2(*reinterpret_cast<__half2*>(&kk[p].y));
                s0 += f0.x; s1 += f0.y; s2 += f1.x; s3 += f1.y;   // v0 = 1
            }
            float sum = (s0 + s1) + (s2 + s3);
            #pragma unroll
            for (int o = 16; o; o >>= 1) sum += __shfl_xor_sync(0xffffffffu, sum, o);
            float u = (sum > 0.f) ? __fdividef(1.0f, sum) : 0.f;
            if (lane == 0) g_u[(b << 10) + i] = u;
            #pragma unroll
            for (int p = 0; p < 8; p++) {
                float2 f0 = __half22float2(*reinterpret_cast<__half2*>(&kk[p].x));
                float2 f1 = __half22float2(*reinterpret_cast<__half2*>(&kk[p].y));
                acc[p * 4 + 0] = fmaf(f0.x, u, acc[p * 4 + 0]);
                acc[p * 4 + 1] = fmaf(f0.y, u, acc[p * 4 + 1]);
                acc[p * 4 + 2] = fmaf(f1.x, u, acc[p * 4 + 2]);
                acc[p * 4 + 3] = fmaf(f1.y, u, acc[p * 4 + 3]);
            }
        }
    }
    __shared__ float sm[8 * 1024];
    #pragma unroll
    for (int p = 0; p < 8; p++) {
        *reinterpret_cast<float4*>(&sm[w * 1024 + p * 128 + lane * 4]) =
            make_float4(acc[p * 4 + 0], acc[p * 4 + 1], acc[p * 4 + 2], acc[p * 4 + 3]);
    }
    __syncthreads();
    int t = threadIdx.x;
    int jmax = npass << 7;
    #pragma unroll
    for (int r = 0; r < 4; r++) {
        int j = r * 256 + t;
        if (j < jmax) {
            float s = 0.f;
            #pragma unroll
            for (int ww = 0; ww < 8; ww++) s += sm[ww * 1024 + j];
            atomicAdd(&g_sb[0][(b << 10) + j], s);
        }
    }
}

// ---------------------------------------------------------------------------
// Fused Sinkhorn step `stage` (1..9), HMMA version with conflict-free strip.
// Block = 16 rows of one batch, 8 warps. grid = (64, 64) (x=strip, y=batch).
// ---------------------------------------------------------------------------
__global__ void __launch_bounds__(256) fused_pass_kernel(const int* __restrict__ nrows,
                                                         const int* __restrict__ ncols,
                                                         int stage) {
    int b  = blockIdx.y;
    int nr = nrows[b];
    int nc = ncols[b];
    int i0 = blockIdx.x << 4;
    if (i0 >= nr || nc == 0) return;
    int npass = (nc + 127) >> 7;
    int ntile = npass << 3;        // number of 16-col tiles
    int jmax  = npass << 7;
    int nrv   = min(16, nr - i0);

    int t = threadIdx.x, lane = t & 31, w = t >> 5;

    __shared__ __align__(16) __half strip[16 * RSTRIDE]; // 33 KB, padded rows
    __shared__ __align__(8)  __half vh[1024];            // v * 2^f as fp16
    __shared__ __align__(8)  __half uh[16];              // u * 2^e as fp16
    __shared__ float sacc[1024];                         // scaled col sums
    __shared__ float spart[128];                         // 8 warps x 16 rowsums
    __shared__ float sred[9];                            // warp vmax + e bcast

    // ---- 1. strip load / zero-fill (row r at byte offset r*2064) ----
    {
        int r  = t >> 4;
        int cb = (t & 15) << 4;                          // byte offset, stride 256
        char* rowbase = reinterpret_cast<char*>(strip) + r * (RSTRIDE * 2);
        if (r < nrv) {
            const char* src = (const char*)(g_K + ((size_t)b << 20) + ((size_t)(i0 + r) << 10));
            uint32_t dst = (uint32_t)__cvta_generic_to_shared(rowbase);
            for (int p = 0; p < npass; p++)
                asm volatile("cp.async.cg.shared.global [%0], [%1], 16;\n"
                             :: "r"(dst + cb + (p << 8)), "l"(src + cb + (p << 8)));
        } else {
            for (int p = 0; p < npass; p++)
                *reinterpret_cast<uint4*>(rowbase + cb + (p << 8)) =
                    make_uint4(0u, 0u, 0u, 0u);
        }
        asm volatile("cp.async.commit_group;\n");
    }

    // ---- 2. v prep with dynamic power-of-2 scaling ----
    float fscale;
    {
        float4 s4 = *reinterpret_cast<const float4*>(&g_sb[stage - 1][(b << 10) + (t << 2)]);
        float v0 = (s4.x > 0.f) ? __fdividef(1.f, s4.x) : 0.f;
        float v1 = (s4.y > 0.f) ? __fdividef(1.f, s4.y) : 0.f;
        float v2 = (s4.z > 0.f) ? __fdividef(1.f, s4.z) : 0.f;
        float v3 = (s4.w > 0.f) ? __fdividef(1.f, s4.w) : 0.f;
        *reinterpret_cast<float4*>(&sacc[t << 2]) = make_float4(0.f, 0.f, 0.f, 0.f);
        float vm = fmaxf(fmaxf(v0, v1), fmaxf(v2, v3));
        #pragma unroll
        for (int o = 16; o; o >>= 1) vm = fmaxf(vm, __shfl_xor_sync(0xffffffffu, vm, o));
        if (lane == 0) sred[w] = vm;
        __syncthreads();
        float vmax = sred[0];
        #pragma unroll
        for (int k = 1; k < 8; k++) vmax = fmaxf(vmax, sred[k]);
        int f = (vmax > 0.f) ? (14 - ilogbf(vmax)) : 0;
        fscale = exp2i(f);
        __half2 h01 = __floats2half2_rn(v0 * fscale, v1 * fscale);
        __half2 h23 = __floats2half2_rn(v2 * fscale, v3 * fscale);
        uint2 packed = make_uint2(*reinterpret_cast<uint32_t*>(&h01),
                                  *reinterpret_cast<uint32_t*>(&h23));
        *reinterpret_cast<uint2*>(&vh[t << 2]) = packed;
    }
    asm volatile("cp.async.wait_group 0;\n");
    __syncthreads();

    // ldmatrix base: lane L -> row (L & 15) at padded stride, +16B for L>=16.
    // Row stride 2064 B => consecutive rows shift 16 B mod 128 => conflict-free.
    uint32_t lm_base = (uint32_t)__cvta_generic_to_shared(strip)
                     + (lane & 15) * (RSTRIDE * 2) + ((lane >> 4) << 4);

    // ---- 3. row pass: D += K_tile x vh_replicated ----
    {
        float c0 = 0.f, c1 = 0.f, c2 = 0.f, c3 = 0.f;
        for (int kt = w; kt < ntile; kt += 8) {
            int j0 = kt << 4;
            uint32_t a0, a1, a2, a3;
            asm volatile("ldmatrix.sync.aligned.m8n8.x4.shared.b16 {%0,%1,%2,%3},[%4];\n"
                         : "=r"(a0), "=r"(a1), "=r"(a2), "=r"(a3)
                         : "r"(lm_base + (j0 << 1)));
            uint32_t b0 = *reinterpret_cast<const uint32_t*>(&vh[j0 + ((lane & 3) << 1)]);
            uint32_t b1 = *reinterpret_cast<const uint32_t*>(&vh[j0 + ((lane & 3) << 1) + 8]);
            asm volatile("mma.sync.aligned.m16n8k16.row.col.f32.f16.f16.f32 "
                         "{%0,%1,%2,%3},{%4,%5,%6,%7},{%8,%9},{%0,%1,%2,%3};\n"
                         : "+f"(c0), "+f"(c1), "+f"(c2), "+f"(c3)
                         : "r"(a0), "r"(a1), "r"(a2), "r"(a3), "r"(b0), "r"(b1));
        }
        if ((lane & 3) == 0) {                // col 0 holders: rowsum*2^f
            spart[(w << 4) + (lane >> 2)]     = c0;   // rows 0-7
            spart[(w << 4) + (lane >> 2) + 8] = c2;   // rows 8-15
        }
    }
    __syncthreads();

    // ---- 4. u from rowsums; per-block scale e; uh ----
    if (t < 16) {
        float D = 0.f;
        #pragma unroll
        for (int ww = 0; ww < 8; ww++) D += spart[(ww << 4) + t];
        float u = (t < nrv && D > 0.f) ? (fscale * __fdividef(1.f, D)) : 0.f;
        if (t < nrv) g_u[(b << 10) + i0 + t] = u;
        float um = u;
        #pragma unroll
        for (int o = 8; o; o >>= 1) um = fmaxf(um, __shfl_xor_sync(0xffffu, um, o));
        int e = (um > 0.f) ? (14 - ilogbf(um)) : 0;
        uh[t] = __float2half_rn(u * exp2i(e));
        if (t == 0) sred[8] = (float)e;
    }
    __syncthreads();
    float descale = exp2i(-(int)sred[8]);

    // ---- 5. col pass: D = uh_broadcast x K_tile^T (ldmatrix.trans) ----
    {
        uint32_t ua0 = *reinterpret_cast<const uint32_t*>(&uh[(lane & 3) << 1]);
        uint32_t ua1 = *reinterpret_cast<const uint32_t*>(&uh[((lane & 3) << 1) + 8]);
        for (int ct = w; ct < ntile; ct += 8) {
            int j0 = ct << 4;
            uint32_t b0, b1, b2, b3;
            asm volatile("ldmatrix.sync.aligned.m8n8.x4.trans.shared.b16 {%0,%1,%2,%3},[%4];\n"
                         : "=r"(b0), "=r"(b1), "=r"(b2), "=r"(b3)
                         : "r"(lm_base + (j0 << 1)));
            float d0 = 0.f, d1 = 0.f, d2 = 0.f, d3 = 0.f;
            asm volatile("mma.sync.aligned.m16n8k16.row.col.f32.f16.f16.f32 "
                         "{%0,%1,%2,%3},{%4,%5,%6,%7},{%8,%9},{%0,%1,%2,%3};\n"
                         : "+f"(d0), "+f"(d1), "+f"(d2), "+f"(d3)
                         : "r"(ua0), "r"(ua0), "r"(ua1), "r"(ua1), "r"(b0), "r"(b1));
            float e0 = 0.f, e1 = 0.f, e2 = 0.f, e3 = 0.f;
            asm volatile("mma.sync.aligned.m16n8k16.row.col.f32.f16.f16.f32 "
                         "{%0,%1,%2,%3},{%4,%5,%6,%7},{%8,%9},{%0,%1,%2,%3};\n"
                         : "+f"(e0), "+f"(e1), "+f"(e2), "+f"(e3)
                         : "r"(ua0), "r"(ua0), "r"(ua1), "r"(ua1), "r"(b2), "r"(b3));
            if (lane < 4) {                  // row 0 of D: cols j0+2l, j0+2l+1
                int j = j0 + (lane << 1);
                sacc[j]     += d0;  sacc[j + 1] += d1;
                sacc[j + 8] += e0;  sacc[j + 9] += e1;
            }
        }
    }
    __syncthreads();

    // ---- 6. epilogue: descale + global atomic ----
    {
        int j = t << 2;
        if (j < jmax) {
            float4 sa = *reinterpret_cast<float4*>(&sacc[j]);
            float* out = &g_sb[stage][(b << 10) + j];
            atomicAdd(&out[0], sa.x * descale);
            atomicAdd(&out[1], sa.y * descale);
            atomicAdd(&out[2], sa.z * descale);
            atomicAdd(&out[3], sa.w * descale);
        }
    }
}

// ---------------------------------------------------------------------------
// Final: out = valid ? u_i * exp(m_ij) * inv(sb[9]_j) : 0 — fp32 exp.
// grid = 4096, block = 256, 16 float4/thread (full 256 MB write).
// ---------------------------------------------------------------------------
__global__ void final_kernel(const float* __restrict__ m,
                             const int* __restrict__ nrows,
                             const int* __restrict__ ncols,
                             float* __restrict__ out) {
    int b   = blockIdx.x >> 6;
    int sub = blockIdx.x & 63;
    int nr = nrows[b];
    int nc = ncols[b];
    const float* mb = m + ((size_t)b << 20);
    float*       ob = out + ((size_t)b << 20);
    const float* sb = &g_sb[NSTAGE - 1][b << 10];

    #pragma unroll
    for (int k = 0; k < 16; k++) {
        int q = sub * 4096 + k * 256 + threadIdx.x;
        int i = q >> 8;
        int j = (q & 255) << 2;
        float4 o;
        if (i >= nr || j >= nc) {
            o = make_float4(0.f, 0.f, 0.f, 0.f);
        } else {
            float4 mm = *reinterpret_cast<const float4*>(mb + ((size_t)q << 2));
            float  u  = g_u[(b << 10) + i];
            float4 s4 = *reinterpret_cast<const float4*>(sb + j);
            float vx = (s4.x > 0.f) ? __fdividef(1.0f, s4.x) : 0.f;
            float vy = (s4.y > 0.f) ? __fdividef(1.0f, s4.y) : 0.f;
            float vz = (s4.z > 0.f) ? __fdividef(1.0f, s4.z) : 0.f;
            float vw = (s4.w > 0.f) ? __fdividef(1.0f, s4.w) : 0.f;
            o.x = __expf(mm.x) * u * vx;
            o.y = __expf(mm.y) * u * vy;
            o.z = __expf(mm.z) * u * vz;
            o.w = __expf(mm.w) * u * vw;
        }
        *reinterpret_cast<float4*>(ob + ((size_t)q << 2)) = o;
    }
}

extern "C" void kernel_launch(void* const* d_in, const int* in_sizes, int n_in,
                              void* d_out, int out_size) {
    const float* m     = (const float*)d_in[0];
    const int*   nrows = (const int*)d_in[1];
    const int*   ncols = (const int*)d_in[2];
    float* out = (float*)d_out;

    init_kernel<<<160, 256>>>();                                   // zero stage bufs
    build_fused_kernel<<<dim3(32, 64), 256>>>(m, nrows, ncols);    // step 1
    for (int t = 1; t <= 9; t++)                                   // steps 2..10
        fused_pass_kernel<<<dim3(64, 64), 256>>>(nrows, ncols, t);
    final_kernel<<<4096, 256>>>(m, nrows, ncols, out);
}

// round 14
// speedup vs baseline: 1.5917x; 1.0579x over previous
#include <cuda_runtime.h>
#include <cuda_fp16.h>
#include <cstdint>

// Sinkhorn, linear domain, fp16-compressed kernel matrix, stage-buffered
// column sums. Persistent-kernel main loop (one launch for all 9 passes,
// counted grid barriers between passes; barrier counters zeroed per replay
// by init_kernel so graph replays are clean).
//   K = valid ? fp16(exp(m)) : 0      (built fused with Sinkhorn step 1, v0=1)
//   step t: u_i = 1 / sum_j K_ij * inv(sb[t-1]_j) ; sb[t]_j += sum_i K_ij u_i
//   out = valid ? u_i * exp(m_ij) * inv(sb[9]_j) : 0
// exp() is a 5th-order FMA polynomial (MUFU was the throughput bound).

#define BB 64
#define NN 1024
#define MM 1024
#define NSTAGE 10

__device__ __half g_K[(size_t)BB * NN * MM];     // 128 MB scratch
__device__ float  g_u[BB * NN];
__device__ float  g_sb[NSTAGE][BB * MM];         // per-stage col-sum buffers
__device__ int    g_barcnt[16];                  // grid-barrier counters

// FMA-pipe exp: x in ~[-9,9]. rel err ~1e-8.
__device__ __forceinline__ float fexp(float x) {
    float y = x * 1.44269504088896f;     // x * log2(e)
    float n = rintf(y);
    float f = y - n;                     // f in [-0.5, 0.5]
    float p = 1.33335581e-3f;
    p = fmaf(p, f, 9.61812910e-3f);
    p = fmaf(p, f, 5.55041087e-2f);
    p = fmaf(p, f, 2.40226507e-1f);
    p = fmaf(p, f, 6.93147181e-1f);
    p = fmaf(p, f, 1.0f);
    return p * __int_as_float(((int)n + 127) << 23);   // * 2^n (exact)
}

// ---------------------------------------------------------------------------
// Zero stage buffers + barrier counters (once per replay). grid=160, blk=256.
// ---------------------------------------------------------------------------
__global__ void init_kernel() {
    float4* p = reinterpret_cast<float4*>(&g_sb[0][0]);
    int idx = blockIdx.x * blockDim.x + threadIdx.x;
    const int total = NSTAGE * BB * MM / 4;
    #pragma unroll
    for (int r = 0; r < 4; r++) {
        int q = idx + r * 40960;
        if (q < total) p[q] = make_float4(0.f, 0.f, 0.f, 0.f);
    }
    if (idx < 16) g_barcnt[idx] = 0;
}

// ---------------------------------------------------------------------------
// Build + Sinkhorn step 1 (v0 = 1): block = 32 rows x 8 warps x 4 rows.
// fexp(m) masked -> fp16 K (zero-padded to 128-col tile boundary), row sums
// -> u1, col partials -> g_sb[0]. grid = (32, 64), block = 256.
// ---------------------------------------------------------------------------
__global__ void __launch_bounds__(256) build_fused_kernel(const float* __restrict__ m,
                                                          const int* __restrict__ nrows,
                                                          const int* __restrict__ ncols) {
    int b  = blockIdx.y;
    int nr = nrows[b];
    int nc = ncols[b];
    int i0 = blockIdx.x * 32;
    if (i0 >= nr || nc == 0) return;
    int npass = (nc + 127) >> 7;

    int lane = threadIdx.x & 31;
    int w    = threadIdx.x >> 5;

    float acc[32];
    #pragma unroll
    for (int k = 0; k < 32; k++) acc[k] = 0.f;

    const float* mb = m + ((size_t)b << 20);
    __half*      Kb = g_K + ((size_t)b << 20);

    #pragma unroll
    for (int q = 0; q < 4; q++) {
        int i = i0 + w * 4 + q;
        if (i < nr) {
            const float* mrow = mb + ((size_t)i << 10);
            __half*      krow = Kb + ((size_t)i << 10);
            uint2 kk[8];
            float s0 = 0.f, s1 = 0.f, s2 = 0.f, s3 = 0.f;
            #pragma unroll
            for (int p = 0; p < 8; p++) {
                if (p < npass) {
                    int j = p * 128 + lane * 4;
                    float4 mv = *reinterpret_cast<const float4*>(mrow + j);
                    float e0 = (j + 0 < nc) ? fexp(mv.x) : 0.f;
                    float e1 = (j + 1 < nc) ? fexp(mv.y) : 0.f;
                    float e2 = (j + 2 < nc) ? fexp(mv.z) : 0.f;
                    float e3 = (j + 3 < nc) ? fexp(mv.w) : 0.f;
                    __half2 h0 = __floats2half2_rn(e0, e1);
                    __half2 h1 = __floats2half2_rn(e2, e3);
                    kk[p].x = *reinterpret_cast<uint32_t*>(&h0);
                    kk[p].y = *reinterpret_cast<uint32_t*>(&h1);
                    *reinterpret_cast<uint2*>(krow + j) = kk[p];
                } else {
                    kk[p] = make_uint2(0u, 0u);
                }
                float2 f0 = __half22float2(*reinterpret_cast<__half2*>(&kk[p].x));
                float2 f1 = __half22float2(*reinterpret_cast<__half2*>(&kk[p].y));
                s0 += f0.x; s1 += f0.y; s2 += f1.x; s3 += f1.y;   // v0 = 1
            }
            float sum = (s0 + s1) + (s2 + s3);
            #pragma unroll
            for (int o = 16; o; o >>= 1) sum += __shfl_xor_sync(0xffffffffu, sum, o);
            float u = (sum > 0.f) ? __fdividef(1.0f, sum) : 0.f;
            if (lane == 0) g_u[(b << 10) + i] = u;
            #pragma unroll
            for (int p = 0; p < 8; p++) {
                float2 f0 = __half22float2(*reinterpret_cast<__half2*>(&kk[p].x));
                float2 f1 = __half22float2(*reinterpret_cast<__half2*>(&kk[p].y));
                acc[p * 4 + 0] = fmaf(f0.x, u, acc[p * 4 + 0]);
                acc[p * 4 + 1] = fmaf(f0.y, u, acc[p * 4 + 1]);
                acc[p * 4 + 2] = fmaf(f1.x, u, acc[p * 4 + 2]);
                acc[p * 4 + 3] = fmaf(f1.y, u, acc[p * 4 + 3]);
            }
        }
    }
    __shared__ float sm[8 * 1024];
    #pragma unroll
    for (int p = 0; p < 8; p++) {
        *reinterpret_cast<float4*>(&sm[w * 1024 + p * 128 + lane * 4]) =
            make_float4(acc[p * 4 + 0], acc[p * 4 + 1], acc[p * 4 + 2], acc[p * 4 + 3]);
    }
    __syncthreads();
    int t = threadIdx.x;
    int jmax = npass << 7;
    #pragma unroll
    for (int r = 0; r < 4; r++) {
        int j = r * 256 + t;
        if (j < jmax) {
            float s = 0.f;
            #pragma unroll
            for (int ww = 0; ww < 8; ww++) s += sm[ww * 1024 + j];
            atomicAdd(&g_sb[0][(b << 10) + j], s);
        }
    }
}

// ---------------------------------------------------------------------------
// Persistent loop: Sinkhorn steps 2..10 (stages 1..9) in one launch.
// Block-uniform job loop over 2048 jobs (64 batches x 32-row chunks) per
// stage; counted grid barrier between stages. Body = R6 two-phase scalar.
// ---------------------------------------------------------------------------
__global__ void __launch_bounds__(256, 3) persistent_kernel(const int* __restrict__ nrows,
                                                            const int* __restrict__ ncols,
                                                            int NB) {
    int lane = threadIdx.x & 31;
    int w    = threadIdx.x >> 5;
    int t    = threadIdx.x;

    __shared__ float sv[1024];        // inverted column potentials
    __shared__ float sm[8 * 1024];    // per-warp column partial staging

    for (int stage = 1; stage <= 9; stage++) {
        for (int job = blockIdx.x; job < 2048; job += NB) {
            int b  = job & 63;
            int i0 = (job >> 6) << 5;
            int nr = nrows[b];
            int nc = ncols[b];
            if (i0 >= nr || nc == 0) continue;      // block-uniform
            int npass = (nc + 127) >> 7;

            // invert col sums of previous stage into smem v
            {
                const float* s_in = &g_sb[stage - 1][b << 10];
                float4 s4 = *reinterpret_cast<const float4*>(s_in + t * 4);
                float4 v4;
                v4.x = (s4.x > 0.f) ? __fdividef(1.0f, s4.x) : 0.f;
                v4.y = (s4.y > 0.f) ? __fdividef(1.0f, s4.y) : 0.f;
                v4.z = (s4.z > 0.f) ? __fdividef(1.0f, s4.z) : 0.f;
                v4.w = (s4.w > 0.f) ? __fdividef(1.0f, s4.w) : 0.f;
                *reinterpret_cast<float4*>(&sv[t * 4]) = v4;
            }
            __syncthreads();

            const __half* Kb = g_K + ((size_t)b << 20);
            int ibase = i0 + w * 4;
            int nrow  = min(4, nr - ibase);

            // phase 1: row sums
            float sums[4] = {0.f, 0.f, 0.f, 0.f};
            for (int p = 0; p < npass; p++) {
                float4 v4 = *reinterpret_cast<const float4*>(&sv[(p << 7) + (lane << 2)]);
                #pragma unroll
                for (int q = 0; q < 4; q++) {
                    if (q < nrow) {
                        uint2 kk = *reinterpret_cast<const uint2*>(
                            Kb + ((size_t)(ibase + q) << 10) + (p << 7) + (lane << 2));
                        float2 f0 = __half22float2(*reinterpret_cast<__half2*>(&kk.x));
                        float2 f1 = __half22float2(*reinterpret_cast<__half2*>(&kk.y));
                        sums[q] += fmaf(f0.x, v4.x, fmaf(f0.y, v4.y,
                                   fmaf(f1.x, v4.z, f1.y * v4.w)));
                    }
                }
            }
            float u[4];
            #pragma unroll
            for (int q = 0; q < 4; q++) {
                float s = sums[q];
                #pragma unroll
                for (int o = 16; o; o >>= 1) s += __shfl_xor_sync(0xffffffffu, s, o);
                u[q] = (s > 0.f) ? __fdividef(1.0f, s) : 0.f;
                if (lane == 0 && q < nrow) g_u[(b << 10) + ibase + q] = u[q];
            }

            // phase 2: column partials (re-read warp's own tile, L1/L2-hot)
            for (int p = 0; p < npass; p++) {
                int j = (p << 7) + (lane << 2);
                float a0 = 0.f, a1 = 0.f, a2 = 0.f, a3 = 0.f;
                #pragma unroll
                for (int q = 0; q < 4; q++) {
                    if (q < nrow) {
                        uint2 kk = *reinterpret_cast<const uint2*>(
                            Kb + ((size_t)(ibase + q) << 10) + j);
                        float2 f0 = __half22float2(*reinterpret_cast<__half2*>(&kk.x));
                        float2 f1 = __half22float2(*reinterpret_cast<__half2*>(&kk.y));
                        a0 = fmaf(f0.x, u[q], a0);
                        a1 = fmaf(f0.y, u[q], a1);
                        a2 = fmaf(f1.x, u[q], a2);
                        a3 = fmaf(f1.y, u[q], a3);
                    }
                }
                *reinterpret_cast<float4*>(&sm[w * 1024 + j]) = make_float4(a0, a1, a2, a3);
            }
            __syncthreads();

            // epilogue: cross-warp sum + global atomic
            int jmax = npass << 7;
            float* s_out = &g_sb[stage][b << 10];
            #pragma unroll
            for (int r = 0; r < 4; r++) {
                int j = r * 256 + t;
                if (j < jmax) {
                    float s = 0.f;
                    #pragma unroll
                    for (int ww = 0; ww < 8; ww++) s += sm[ww * 1024 + j];
                    atomicAdd(&s_out[j], s);
                }
            }
            __syncthreads();   // sm/sv safe to overwrite next job
        }

        // grid barrier between stages (counters pre-zeroed by init_kernel)
        if (stage < 9) {
            __syncthreads();
            if (t == 0) {
                __threadfence();
                atomicAdd(&g_barcnt[stage], 1);
                volatile int* bp = &g_barcnt[stage];
                while (*bp < NB) __nanosleep(64);
            }
            __syncthreads();
        }
    }
}

// ---------------------------------------------------------------------------
// Final: out = valid ? u_i * fexp(m_ij) * inv(sb[9]_j) : 0.
// grid = 4096, block = 256, 16 float4/thread (full 256 MB write).
// ---------------------------------------------------------------------------
__global__ void final_kernel(const float* __restrict__ m,
                             const int* __restrict__ nrows,
                             const int* __restrict__ ncols,
                             float* __restrict__ out) {
    int b   = blockIdx.x >> 6;
    int sub = blockIdx.x & 63;
    int nr = nrows[b];
    int nc = ncols[b];
    const float* mb = m + ((size_t)b << 20);
    float*       ob = out + ((size_t)b << 20);
    const float* sb = &g_sb[NSTAGE - 1][b << 10];

    #pragma unroll
    for (int k = 0; k < 16; k++) {
        int q = sub * 4096 + k * 256 + threadIdx.x;
        int i = q >> 8;
        int j = (q & 255) << 2;
        float4 o;
        if (i >= nr || j >= nc) {
            o = make_float4(0.f, 0.f, 0.f, 0.f);
        } else {
            float4 mm = *reinterpret_cast<const float4*>(mb + ((size_t)q << 2));
            float  u  = g_u[(b << 10) + i];
            float4 s4 = *reinterpret_cast<const float4*>(sb + j);
            float vx = (s4.x > 0.f) ? __fdividef(1.0f, s4.x) : 0.f;
            float vy = (s4.y > 0.f) ? __fdividef(1.0f, s4.y) : 0.f;
            float vz = (s4.z > 0.f) ? __fdividef(1.0f, s4.z) : 0.f;
            float vw = (s4.w > 0.f) ? __fdividef(1.0f, s4.w) : 0.f;
            // s==0 exactly for j >= nc -> tail of boundary float4 zeroed.
            o.x = fexp(mm.x) * u * vx;
            o.y = fexp(mm.y) * u * vy;
            o.z = fexp(mm.z) * u * vz;
            o.w = fexp(mm.w) * u * vw;
        }
        *reinterpret_cast<float4*>(ob + ((size_t)q << 2)) = o;
    }
}

extern "C" void kernel_launch(void* const* d_in, const int* in_sizes, int n_in,
                              void* d_out, int out_size) {
    const float* m     = (const float*)d_in[0];
    const int*   nrows = (const int*)d_in[1];
    const int*   ncols = (const int*)d_in[2];
    float* out = (float*)d_out;

    // Size the persistent grid so all blocks are co-resident (host-side
    // queries only; no allocations, deterministic, capture-safe).
    int dev = 0;
    cudaGetDevice(&dev);
    int nsm = 0;
    cudaDeviceGetAttribute(&nsm, cudaDevAttrMultiProcessorCount, dev);
    int occ = 0;
    cudaOccupancyMaxActiveBlocksPerMultiprocessor(&occ, persistent_kernel, 256, 0);
    int NB = nsm * occ;
    if (NB > 2048) NB = 2048;
    if (NB < 1)    NB = 1;

    init_kernel<<<160, 256>>>();                                   // zero sb + barriers
    build_fused_kernel<<<dim3(32, 64), 256>>>(m, nrows, ncols);    // step 1
    persistent_kernel<<<NB, 256>>>(nrows, ncols, NB);              // steps 2..10
    final_kernel<<<4096, 256>>>(m, nrows, ncols, out);
}